// round 5
// baseline (speedup 1.0000x reference)
#include <cuda_runtime.h>

// EfronLossPenalty — bucketized Efron Cox loss, times in [0, 8192).
// Per-tie-block rank sum is permutation-invariant -> only (d, ers, rss) per
// bucket matter. Block log-sum collapses via falling factorial:
//   sum_{l=0}^{d-1} log(rss - l*s) = d*log(s) + lgamma(x+1) - lgamma(x-d+1),
// evaluated with a cancellation-free float Stirling difference.
//
// Accumulation: ONE packed 64-bit RED per element into g_P[rep][bin]:
//   bits [52:64) event count | [26:52) fix10 event-risk | [0:26) fix10 total-risk.
// Post-pass fused into the same kernel: last 64 blocks to finish become the
// post roles (reduce + suffix scan + Efron terms + final scalar).

#define NBINS 8192
#define NREP  8
#define MASK26 ((1ULL << 26) - 1ULL)
#define FIX 1024.0f
#define GRID 1184
#define NROLE 64
#define THREADS 256

// Static scratch — zero at module load; every launch restores the all-zero
// invariant before exiting (graph-replay safe).
__device__ unsigned long long g_P[NREP * NBINS];
__device__ float g_chunk[NROLE];
__device__ float g_elr;
__device__ float g_terms;
__device__ float g_nev;
__device__ unsigned g_done0;   // accum completion
__device__ unsigned g_done1;   // chunk publish among roles
__device__ unsigned g_done2;   // terms completion among roles

__device__ __forceinline__ float block_reduce_sum(float v) {
    __shared__ float s[32];
    int lane = threadIdx.x & 31;
    int wid  = threadIdx.x >> 5;
    #pragma unroll
    for (int o = 16; o > 0; o >>= 1) v += __shfl_down_sync(0xffffffffu, v, o);
    if (lane == 0) s[wid] = v;
    __syncthreads();
    int nw = (blockDim.x + 31) >> 5;
    v = (threadIdx.x < nw) ? s[threadIdx.x] : 0.0f;
    if (wid == 0) {
        #pragma unroll
        for (int o = 16; o > 0; o >>= 1) v += __shfl_down_sync(0xffffffffu, v, o);
    }
    __syncthreads();   // protect s[] against reuse
    return v;          // valid in thread 0
}

__device__ __forceinline__ void accum_one(int t, int e, float x, unsigned rep, float& elr) {
    float w = __expf(x);
    unsigned wi = (unsigned)(w * FIX + 0.5f);
    unsigned long long pk = (unsigned long long)wi
                          + ((unsigned long long)(wi * (unsigned)e) << 26)
                          + ((unsigned long long)(unsigned)e << 52);
    atomicAdd(&g_P[rep * NBINS + t], pk);   // no return use -> REDG
    elr += e ? x : 0.0f;
}

__global__ void __launch_bounds__(THREADS) k_fused(
        const int* __restrict__ times, const int* __restrict__ events,
        const float* __restrict__ lr, int n,
        float* __restrict__ out, int out_n) {
    int tid = blockIdx.x * THREADS + threadIdx.x;
    int stride = gridDim.x * THREADS;
    unsigned rep = ((unsigned)(tid >> 5)) & (NREP - 1);   // per-warp replica row

    // ================= accumulation =================
    const int4*   t4 = (const int4*)times;
    const int4*   e4 = (const int4*)events;
    const float4* l4 = (const float4*)lr;
    int n4 = n >> 2;

    float elr = 0.0f;
    for (int i = tid; i < n4; i += stride) {
        int4   tv = t4[i];
        int4   ev = e4[i];
        float4 lv = l4[i];
        accum_one(tv.x, ev.x, lv.x, rep, elr);
        accum_one(tv.y, ev.y, lv.y, rep, elr);
        accum_one(tv.z, ev.z, lv.z, rep, elr);
        accum_one(tv.w, ev.w, lv.w, rep, elr);
    }
    int base = n4 << 2;
    int rem  = n - base;
    if (tid < rem) accum_one(times[base + tid], events[base + tid], lr[base + tid], rep, elr);

    float bsum = block_reduce_sum(elr);
    if (threadIdx.x == 0 && bsum != 0.0f) atomicAdd(&g_elr, bsum);

    // ============ completion / role assignment ============
    __threadfence();
    __shared__ unsigned s_prev;
    if (threadIdx.x == 0) s_prev = atomicAdd(&g_done0, 1u);
    __syncthreads();
    unsigned prev = s_prev;
    if (prev < (unsigned)(gridDim.x - NROLE)) return;   // non-role blocks exit
    int role = (int)(prev - (gridDim.x - NROLE));       // 0..63, unique

    // wait for ALL blocks to finish accumulation (roles are resident; others
    // are running or done -> no deadlock)
    if (threadIdx.x == 0) {
        while (*((volatile unsigned*)&g_done0) < gridDim.x) { }
    }
    __syncthreads();
    __threadfence();

    // ================= post: reduce + zero =================
    int b = role * 128 + (threadIdx.x & 127);   // bucket, valid for tid<128
    bool owner = (threadIdx.x < 128);

    int   d = 0;
    float ers = 0.0f, risk = 0.0f;
    if (owner) {
        unsigned long long psum = 0ULL;
        #pragma unroll
        for (int r = 0; r < NREP; r++) {
            int idx = r * NBINS + b;
            psum += g_P[idx];
            g_P[idx] = 0ULL;           // restore zero invariant
        }
        d    = (int)(psum >> 52);
        ers  = (float)((psum >> 26) & MASK26) * (1.0f / FIX);
        risk = (float)(psum & MASK26) * (1.0f / FIX);
    }

    // ============ cross-role suffix scan of risk ============
    float csum = block_reduce_sum(owner ? risk : 0.0f);
    if (threadIdx.x == 0) {
        g_chunk[role] = csum;
        __threadfence();
        atomicAdd(&g_done1, 1u);
        while (*((volatile unsigned*)&g_done1) < NROLE) { }
    }
    __syncthreads();
    __threadfence();

    float suffix_base = 0.0f;
    for (int j = role + 1; j < NROLE; j++) suffix_base += g_chunk[j];

    __shared__ float sv[128];
    if (owner) sv[threadIdx.x] = risk;
    __syncthreads();
    for (int off = 1; off < 128; off <<= 1) {
        float add = (owner && threadIdx.x + off < 128) ? sv[threadIdx.x + off] : 0.0f;
        __syncthreads();
        if (owner) sv[threadIdx.x] += add;
        __syncthreads();
    }
    float rss = owner ? (suffix_base + sv[threadIdx.x]) : 0.0f;

    // ================= Efron terms (float Stirling) =================
    float term = 0.0f;
    if (owner && d == 1) {
        term = logf(rss + 1e-12f);
    } else if (owner && d > 1) {
        float s  = ers / (float)d;
        float x  = rss / s;
        float a  = x + 1.0f;
        float bb = x - (float)d + 1.0f;
        if (bb > 0.5f) {
            // F(z) = (z-1/2)ln z - z + 1/(12z); F(a)-F(b) without cancellation:
            float la = logf(a), lb = logf(bb);
            float L  = 0.5f * (la + lb);
            float m  = 0.5f * (a + bb);
            float dlt = log1pf((float)d / bb);
            term = (float)d * (logf(s) + L - 1.0f)
                 + (m - 0.5f) * dlt
                 + (1.0f / 12.0f) * (1.0f / a - 1.0f / bb);
        } else {   // near-clamp fallback (matches reference per-term max(.,eps))
            float sum = 0.0f;
            for (int l = 0; l < d; l++)
                sum += __logf(fmaxf(rss - (float)l * s, 1e-12f));
            term = sum;
        }
    }
    float tsum = block_reduce_sum(term);
    if (threadIdx.x == 0 && tsum != 0.0f) atomicAdd(&g_terms, tsum);
    float dsum = block_reduce_sum(owner ? (float)d : 0.0f);
    if (threadIdx.x == 0 && dsum != 0.0f) atomicAdd(&g_nev, dsum);

    // ================= finalize (last role) =================
    __threadfence();
    __shared__ bool s_last;
    __syncthreads();
    if (threadIdx.x == 0) {
        unsigned p2 = atomicAdd(&g_done2, 1u);
        s_last = (p2 == NROLE - 1);
    }
    __syncthreads();
    if (!s_last) return;

    __threadfence();
    float terms = *((volatile float*)&g_terms);
    float elrT  = *((volatile float*)&g_elr);
    float nev   = *((volatile float*)&g_nev);
    float val   = (terms - elrT) / fmaxf(nev, 1.0f);
    for (int i = threadIdx.x; i < out_n; i += THREADS) out[i] = val;

    if (threadIdx.x == 0) {   // restore all-zero invariant for next replay
        g_elr = 0.0f; g_terms = 0.0f; g_nev = 0.0f;
        g_done0 = 0u; g_done1 = 0u; g_done2 = 0u;
    }
}

extern "C" void kernel_launch(void* const* d_in, const int* in_sizes, int n_in,
                              void* d_out, int out_size) {
    const int*   times  = (const int*)d_in[0];
    const int*   events = (const int*)d_in[1];
    const float* lr     = (const float*)d_in[2];
    float*       out    = (float*)d_out;
    int n = in_sizes[0];

    k_fused<<<GRID, THREADS>>>(times, events, lr, n, out, out_size);
}

// round 6
// speedup vs baseline: 1.0465x; 1.0465x over previous
#include <cuda_runtime.h>

// EfronLossPenalty — bucketized Efron Cox loss, times in [0, 8192).
// Per-tie-block rank sum is permutation-invariant -> only (d, ers, rss) per
// bucket matter. Block log-sum collapses via falling factorial:
//   sum_{l=0}^{d-1} log(rss - l*s) = d*log(s) + lgamma(x+1) - lgamma(x-d+1),
// evaluated with a cancellation-free float Stirling difference.
//
// Accumulation: ONE packed 64-bit RED per element into g_P[rep][bin]:
//   bits [52:64) event count | [26:52) fix10 event-risk | [0:26) fix10 total-risk.
// NREP=16 replica rows (128K counters): R5 showed NREP=8 (64K counters)
// roughly doubles accum time via same-address L2-atomic serialization.
// Post-pass fused: the LAST 64 blocks to finish accumulation become post roles
// (replica reduce + suffix scan + Efron terms + final scalar).

#define NBINS 8192
#define NREP  16
#define MASK26 ((1ULL << 26) - 1ULL)
#define FIX 1024.0f
#define GRID 1184
#define NROLE 64
#define THREADS 256

// Static scratch — zero at module load; every launch restores the all-zero
// invariant before exiting (graph-replay safe).
__device__ unsigned long long g_P[NREP * NBINS];
__device__ float g_chunk[NROLE];
__device__ float g_elr;
__device__ float g_terms;
__device__ float g_nev;
__device__ unsigned g_done0;   // accum completion
__device__ unsigned g_done1;   // chunk publish among roles
__device__ unsigned g_done2;   // terms completion among roles

__device__ __forceinline__ float block_reduce_sum(float v) {
    __shared__ float s[32];
    int lane = threadIdx.x & 31;
    int wid  = threadIdx.x >> 5;
    #pragma unroll
    for (int o = 16; o > 0; o >>= 1) v += __shfl_down_sync(0xffffffffu, v, o);
    if (lane == 0) s[wid] = v;
    __syncthreads();
    int nw = (blockDim.x + 31) >> 5;
    v = (threadIdx.x < nw) ? s[threadIdx.x] : 0.0f;
    if (wid == 0) {
        #pragma unroll
        for (int o = 16; o > 0; o >>= 1) v += __shfl_down_sync(0xffffffffu, v, o);
    }
    __syncthreads();   // protect s[] against reuse
    return v;          // valid in thread 0
}

__device__ __forceinline__ void accum_one(int t, int e, float x, unsigned rep, float& elr) {
    float w = __expf(x);
    unsigned wi = (unsigned)(w * FIX + 0.5f);
    unsigned long long pk = (unsigned long long)wi
                          + ((unsigned long long)(wi * (unsigned)e) << 26)
                          + ((unsigned long long)(unsigned)e << 52);
    atomicAdd(&g_P[rep * NBINS + t], pk);   // no return use -> REDG
    elr += e ? x : 0.0f;
}

__global__ void __launch_bounds__(THREADS) k_fused(
        const int* __restrict__ times, const int* __restrict__ events,
        const float* __restrict__ lr, int n,
        float* __restrict__ out, int out_n) {
    int tid = blockIdx.x * THREADS + threadIdx.x;
    int stride = gridDim.x * THREADS;
    unsigned rep = ((unsigned)(tid >> 5)) & (NREP - 1);   // per-warp replica row

    // ================= accumulation =================
    const int4*   t4 = (const int4*)times;
    const int4*   e4 = (const int4*)events;
    const float4* l4 = (const float4*)lr;
    int n4 = n >> 2;

    float elr = 0.0f;
    for (int i = tid; i < n4; i += stride) {
        int4   tv = t4[i];
        int4   ev = e4[i];
        float4 lv = l4[i];
        accum_one(tv.x, ev.x, lv.x, rep, elr);
        accum_one(tv.y, ev.y, lv.y, rep, elr);
        accum_one(tv.z, ev.z, lv.z, rep, elr);
        accum_one(tv.w, ev.w, lv.w, rep, elr);
    }
    int base = n4 << 2;
    int rem  = n - base;
    if (tid < rem) accum_one(times[base + tid], events[base + tid], lr[base + tid], rep, elr);

    float bsum = block_reduce_sum(elr);
    if (threadIdx.x == 0 && bsum != 0.0f) atomicAdd(&g_elr, bsum);

    // ============ completion / role assignment ============
    __threadfence();
    __shared__ unsigned s_prev;
    if (threadIdx.x == 0) s_prev = atomicAdd(&g_done0, 1u);
    __syncthreads();
    unsigned prev = s_prev;
    if (prev < (unsigned)(gridDim.x - NROLE)) return;   // non-role blocks exit
    int role = (int)(prev - (gridDim.x - NROLE));       // 0..63, unique

    // wait for ALL blocks to finish accumulation (roles are the last 64 to
    // arrive; everyone else is already done or running -> no deadlock)
    if (threadIdx.x == 0) {
        while (*((volatile unsigned*)&g_done0) < gridDim.x) { __nanosleep(64); }
    }
    __syncthreads();
    __threadfence();

    // ================= post: reduce + zero =================
    int b = role * 128 + (threadIdx.x & 127);   // bucket, owners are tid<128
    bool owner = (threadIdx.x < 128);

    int   d = 0;
    float ers = 0.0f, risk = 0.0f;
    if (owner) {
        unsigned long long psum = 0ULL;
        #pragma unroll
        for (int r = 0; r < NREP; r++) {
            int idx = r * NBINS + b;
            psum += g_P[idx];
            g_P[idx] = 0ULL;           // restore zero invariant
        }
        d    = (int)(psum >> 52);
        ers  = (float)((psum >> 26) & MASK26) * (1.0f / FIX);
        risk = (float)(psum & MASK26) * (1.0f / FIX);
    }

    // ============ cross-role suffix scan of risk ============
    float csum = block_reduce_sum(owner ? risk : 0.0f);
    if (threadIdx.x == 0) {
        g_chunk[role] = csum;
        __threadfence();
        atomicAdd(&g_done1, 1u);
        while (*((volatile unsigned*)&g_done1) < NROLE) { __nanosleep(32); }
    }
    __syncthreads();
    __threadfence();

    float suffix_base = 0.0f;
    for (int j = role + 1; j < NROLE; j++) suffix_base += g_chunk[j];

    __shared__ float sv[128];
    if (owner) sv[threadIdx.x] = risk;
    __syncthreads();
    for (int off = 1; off < 128; off <<= 1) {
        float add = (owner && threadIdx.x + off < 128) ? sv[threadIdx.x + off] : 0.0f;
        __syncthreads();
        if (owner) sv[threadIdx.x] += add;
        __syncthreads();
    }
    float rss = owner ? (suffix_base + sv[threadIdx.x]) : 0.0f;

    // ================= Efron terms (float Stirling) =================
    float term = 0.0f;
    if (owner && d == 1) {
        term = logf(rss + 1e-12f);
    } else if (owner && d > 1) {
        float s  = ers / (float)d;
        float x  = rss / s;
        float a  = x + 1.0f;
        float bb = x - (float)d + 1.0f;
        if (bb > 0.5f) {
            // F(z) = (z-1/2)ln z - z + 1/(12z); F(a)-F(b) without cancellation:
            float la = logf(a), lb = logf(bb);
            float L  = 0.5f * (la + lb);
            float m  = 0.5f * (a + bb);
            float dlt = log1pf((float)d / bb);
            term = (float)d * (logf(s) + L - 1.0f)
                 + (m - 0.5f) * dlt
                 + (1.0f / 12.0f) * (1.0f / a - 1.0f / bb);
        } else {   // near-clamp fallback (matches reference per-term max(.,eps))
            float sum = 0.0f;
            for (int l = 0; l < d; l++)
                sum += __logf(fmaxf(rss - (float)l * s, 1e-12f));
            term = sum;
        }
    }
    float tsum = block_reduce_sum(term);
    if (threadIdx.x == 0 && tsum != 0.0f) atomicAdd(&g_terms, tsum);
    float dsum = block_reduce_sum(owner ? (float)d : 0.0f);
    if (threadIdx.x == 0 && dsum != 0.0f) atomicAdd(&g_nev, dsum);

    // ================= finalize (last role) =================
    __threadfence();
    __shared__ bool s_last;
    __syncthreads();
    if (threadIdx.x == 0) {
        unsigned p2 = atomicAdd(&g_done2, 1u);
        s_last = (p2 == NROLE - 1);
    }
    __syncthreads();
    if (!s_last) return;

    __threadfence();
    float terms = *((volatile float*)&g_terms);
    float elrT  = *((volatile float*)&g_elr);
    float nev   = *((volatile float*)&g_nev);
    float val   = (terms - elrT) / fmaxf(nev, 1.0f);
    for (int i = threadIdx.x; i < out_n; i += THREADS) out[i] = val;

    if (threadIdx.x == 0) {   // restore all-zero invariant for next replay
        g_elr = 0.0f; g_terms = 0.0f; g_nev = 0.0f;
        g_done0 = 0u; g_done1 = 0u; g_done2 = 0u;
    }
}

extern "C" void kernel_launch(void* const* d_in, const int* in_sizes, int n_in,
                              void* d_out, int out_size) {
    const int*   times  = (const int*)d_in[0];
    const int*   events = (const int*)d_in[1];
    const float* lr     = (const float*)d_in[2];
    float*       out    = (float*)d_out;
    int n = in_sizes[0];

    k_fused<<<GRID, THREADS>>>(times, events, lr, n, out, out_size);
}

// round 7
// speedup vs baseline: 1.4477x; 1.3834x over previous
#include <cuda_runtime.h>

// EfronLossPenalty — bucketized Efron Cox loss, times in [0, 8192).
// Only per-bucket (d, ers, rss) matter; block log-sum via falling factorial
// -> cancellation-free float Stirling difference.
//
// Accumulation: ONE branch-free 32-bit RED per element into g_C:
//   bank 0 (non-events): fix16 total-risk sum
//   bank 1 (events):     (count << 24) | fix10 event-risk sum
// bank select folded into the address (idx += e*NREP*NBINS), value via SEL.
// Two-kernel structure (R4-proven; fused single-kernel variants measured
// 26-38 us slower in R5/R6 due to a pathological software-barrier tail).

#define NBINS 8192
#define NREP  16
#define BANK  (NREP * NBINS)
#define FIX_NE 65536.0f
#define FIX_EV 1024.0f
#define POST_BLOCKS 64
#define POST_THREADS 128

// Static scratch — zero at module load; every launch restores the all-zero
// invariant before exiting (graph-replay safe).
__device__ unsigned g_C[2 * BANK];
__device__ float g_chunk[POST_BLOCKS];
__device__ float g_elr;
__device__ float g_terms;
__device__ float g_nev;
__device__ unsigned g_done1;
__device__ unsigned g_done2;

__device__ __forceinline__ float block_reduce_sum(float v) {
    __shared__ float s[32];
    int lane = threadIdx.x & 31;
    int wid  = threadIdx.x >> 5;
    #pragma unroll
    for (int o = 16; o > 0; o >>= 1) v += __shfl_down_sync(0xffffffffu, v, o);
    if (lane == 0) s[wid] = v;
    __syncthreads();
    int nw = (blockDim.x + 31) >> 5;
    v = (threadIdx.x < nw) ? s[threadIdx.x] : 0.0f;
    if (wid == 0) {
        #pragma unroll
        for (int o = 16; o > 0; o >>= 1) v += __shfl_down_sync(0xffffffffu, v, o);
    }
    __syncthreads();   // protect s[] against reuse
    return v;          // valid in thread 0
}

__device__ __forceinline__ void accum_one(int t, int e, float x, unsigned rep, float& elr) {
    float w = __expf(x);
    unsigned wi_ne = (unsigned)(w * FIX_NE + 0.5f);
    unsigned wi_ev = (1u << 24) + (unsigned)(w * FIX_EV + 0.5f);
    unsigned idx = rep * NBINS + (unsigned)t + (unsigned)e * BANK;
    unsigned val = e ? wi_ev : wi_ne;
    atomicAdd(&g_C[idx], val);           // no return use -> REDG.32
    elr += e ? x : 0.0f;
}

__global__ void __launch_bounds__(256) k_accum(
        const int* __restrict__ times, const int* __restrict__ events,
        const float* __restrict__ lr, int n) {
    int tid = blockIdx.x * blockDim.x + threadIdx.x;
    int stride = gridDim.x * blockDim.x;
    unsigned rep = ((unsigned)(tid >> 5)) & (NREP - 1);   // per-warp replica row

    const int4*   t4 = (const int4*)times;
    const int4*   e4 = (const int4*)events;
    const float4* l4 = (const float4*)lr;
    int n4 = n >> 2;

    float elr = 0.0f;
    for (int i = tid; i < n4; i += stride) {
        int4   tv = t4[i];
        int4   ev = e4[i];
        float4 lv = l4[i];
        accum_one(tv.x, ev.x, lv.x, rep, elr);
        accum_one(tv.y, ev.y, lv.y, rep, elr);
        accum_one(tv.z, ev.z, lv.z, rep, elr);
        accum_one(tv.w, ev.w, lv.w, rep, elr);
    }
    int base = n4 << 2;
    int rem  = n - base;
    if (tid < rem) accum_one(times[base + tid], events[base + tid], lr[base + tid], rep, elr);

    float bsum = block_reduce_sum(elr);
    if (threadIdx.x == 0 && bsum != 0.0f) atomicAdd(&g_elr, bsum);
}

// Fused post-pass: replica reduce (+ re-zero), cross-block suffix scan,
// per-bucket Efron terms (float Stirling), final scalar.
// 64 blocks x 128 threads, one bucket per thread; all blocks resident.
__global__ void __launch_bounds__(POST_THREADS) k_post(float* __restrict__ out, int out_n) {
    int b = blockIdx.x * POST_THREADS + threadIdx.x;   // bucket 0..8191

    // --- phase 1: reduce over replicas + banks, restore zeros ---
    unsigned ne_fix = 0u;       // fix16 non-event risk
    unsigned cnt = 0u;          // event count
    unsigned ers_fix = 0u;      // fix10 event risk
    #pragma unroll
    for (int r = 0; r < NREP; r++) {
        int idx = r * NBINS + b;
        unsigned v0 = g_C[idx];          g_C[idx] = 0u;
        unsigned v1 = g_C[idx + BANK];   g_C[idx + BANK] = 0u;
        ne_fix  += v0;
        cnt     += v1 >> 24;
        ers_fix += v1 & 0x00FFFFFFu;
    }
    int   d    = (int)cnt;
    float ers  = (float)ers_fix * (1.0f / FIX_EV);
    float risk = (float)ne_fix * (1.0f / FIX_NE) + ers;

    // --- phase 2: cross-block suffix scan of risk ---
    float csum = block_reduce_sum(risk);
    if (threadIdx.x == 0) {
        g_chunk[blockIdx.x] = csum;
        __threadfence();
        atomicAdd(&g_done1, 1u);
        while (*((volatile unsigned*)&g_done1) < gridDim.x) { }
    }
    __syncthreads();
    __threadfence();

    float suffix_base = 0.0f;
    for (int j = blockIdx.x + 1; j < POST_BLOCKS; j++) suffix_base += g_chunk[j];

    __shared__ float sv[POST_THREADS];
    sv[threadIdx.x] = risk;
    __syncthreads();
    for (int off = 1; off < POST_THREADS; off <<= 1) {
        float add = (threadIdx.x + off < POST_THREADS) ? sv[threadIdx.x + off] : 0.0f;
        __syncthreads();
        sv[threadIdx.x] += add;
        __syncthreads();
    }
    float rss = suffix_base + sv[threadIdx.x];   // inclusive suffix sum at bucket b

    // --- phase 3: Efron terms (all-float, cancellation-free) ---
    float term = 0.0f;
    if (d == 1) {
        term = logf(rss + 1e-12f);
    } else if (d > 1) {
        float s  = ers / (float)d;
        float x  = rss / s;
        float a  = x + 1.0f;
        float bb = x - (float)d + 1.0f;
        if (bb > 0.5f) {
            // F(z) = (z-1/2)ln z - z + 1/(12z); F(a)-F(b) without cancellation:
            float la = logf(a), lb = logf(bb);
            float L  = 0.5f * (la + lb);
            float m  = 0.5f * (a + bb);
            float dlt = log1pf((float)d / bb);
            term = (float)d * (logf(s) + L - 1.0f)
                 + (m - 0.5f) * dlt
                 + (1.0f / 12.0f) * (1.0f / a - 1.0f / bb);
        } else {   // near-clamp fallback (matches reference per-term max(.,eps))
            float sum = 0.0f;
            for (int l = 0; l < d; l++)
                sum += __logf(fmaxf(rss - (float)l * s, 1e-12f));
            term = sum;
        }
    }
    float tsum = block_reduce_sum(term);
    if (threadIdx.x == 0 && tsum != 0.0f) atomicAdd(&g_terms, tsum);
    float dsum = block_reduce_sum((float)d);
    if (threadIdx.x == 0 && dsum != 0.0f) atomicAdd(&g_nev, dsum);

    // --- phase 4: last block finalizes and resets scalars ---
    __threadfence();
    __shared__ bool s_last;
    __syncthreads();
    if (threadIdx.x == 0) {
        unsigned prev = atomicAdd(&g_done2, 1u);
        s_last = (prev == gridDim.x - 1);
    }
    __syncthreads();
    if (!s_last) return;

    __threadfence();
    float terms = *((volatile float*)&g_terms);
    float elr   = *((volatile float*)&g_elr);
    float nev   = *((volatile float*)&g_nev);
    float val   = (terms - elr) / fmaxf(nev, 1.0f);
    for (int i = threadIdx.x; i < out_n; i += POST_THREADS) out[i] = val;

    if (threadIdx.x == 0) {   // restore all-zero invariant for next replay
        g_elr = 0.0f; g_terms = 0.0f; g_nev = 0.0f;
        g_done1 = 0u; g_done2 = 0u;
    }
}

extern "C" void kernel_launch(void* const* d_in, const int* in_sizes, int n_in,
                              void* d_out, int out_size) {
    const int*   times  = (const int*)d_in[0];
    const int*   events = (const int*)d_in[1];
    const float* lr     = (const float*)d_in[2];
    float*       out    = (float*)d_out;
    int n = in_sizes[0];

    k_accum<<<1184, 256>>>(times, events, lr, n);
    k_post <<<POST_BLOCKS, POST_THREADS>>>(out, out_size);
}

// round 9
// speedup vs baseline: 1.5316x; 1.0579x over previous
#include <cuda_runtime.h>

// EfronLossPenalty — bucketized Efron Cox loss, times in [0, 8192).
// Only per-bucket (d, ers, rss) matter; block log-sum via falling factorial
// -> cancellation-free float Stirling difference.
//
// Accumulation: ONE branch-free 32-bit RED per element into g_C:
//   bank 0 (non-events): fix16 total-risk sum
//   bank 1 (events):     (count << 24) | fix10 event-risk sum
// Single F2I per element: scale selected BEFORE the convert, count tag added
// as an integer. Two-kernel structure (fused variants measured 26-38 us
// slower in R5/R6); NREP=16 (contention flat at >=128K counters per R4/R5/R7).

#define NBINS 8192
#define NREP  16
#define BANK  (NREP * NBINS)
#define FIX_NE 65536.0f
#define FIX_EV 1024.0f
#define POST_BLOCKS 64
#define POST_THREADS 128

// Static scratch — zero at module load; every launch restores the all-zero
// invariant before exiting (graph-replay safe).
__device__ unsigned g_C[2 * BANK];
__device__ float g_chunk[POST_BLOCKS];
__device__ float g_elr;
__device__ float g_terms;
__device__ float g_nev;
__device__ unsigned g_done1;
__device__ unsigned g_done2;

__device__ __forceinline__ float block_reduce_sum(float v) {
    __shared__ float s[32];
    int lane = threadIdx.x & 31;
    int wid  = threadIdx.x >> 5;
    #pragma unroll
    for (int o = 16; o > 0; o >>= 1) v += __shfl_down_sync(0xffffffffu, v, o);
    if (lane == 0) s[wid] = v;
    __syncthreads();
    int nw = (blockDim.x + 31) >> 5;
    v = (threadIdx.x < nw) ? s[threadIdx.x] : 0.0f;
    if (wid == 0) {
        #pragma unroll
        for (int o = 16; o > 0; o >>= 1) v += __shfl_down_sync(0xffffffffu, v, o);
    }
    __syncthreads();   // protect s[] against reuse
    return v;          // valid in thread 0
}

__device__ __forceinline__ void accum_one(int t, int e, float x, unsigned repbase, float& elr) {
    float w = __expf(x);
    float scale = e ? FIX_EV : FIX_NE;            // FSEL
    unsigned wi = (unsigned)fmaf(w, scale, 0.5f); // one FFMA + one F2I
    unsigned val = wi + ((unsigned)e << 24);      // count tag (0 for non-events)
    unsigned idx = repbase + (unsigned)t + (unsigned)e * (unsigned)BANK;
    atomicAdd(&g_C[idx], val);                    // no return use -> REDG.32
    elr += e ? x : 0.0f;
}

__global__ void __launch_bounds__(256) k_accum(
        const int* __restrict__ times, const int* __restrict__ events,
        const float* __restrict__ lr, int n) {
    int tid = blockIdx.x * blockDim.x + threadIdx.x;
    int stride = gridDim.x * blockDim.x;
    unsigned repbase = (((unsigned)(tid >> 5)) & (NREP - 1)) * NBINS;

    const int4*   t4 = (const int4*)times;
    const int4*   e4 = (const int4*)events;
    const float4* l4 = (const float4*)lr;
    int n4 = n >> 2;

    float elr = 0.0f;
    int i = tid;
    // 8 elements per iteration: two int4/float4 triplets in flight (deeper MLP)
    for (; i + stride < n4; i += 2 * stride) {
        int4   ta = t4[i],          tb = t4[i + stride];
        int4   ea = e4[i],          eb = e4[i + stride];
        float4 la = l4[i],          lb = l4[i + stride];
        accum_one(ta.x, ea.x, la.x, repbase, elr);
        accum_one(ta.y, ea.y, la.y, repbase, elr);
        accum_one(ta.z, ea.z, la.z, repbase, elr);
        accum_one(ta.w, ea.w, la.w, repbase, elr);
        accum_one(tb.x, eb.x, lb.x, repbase, elr);
        accum_one(tb.y, eb.y, lb.y, repbase, elr);
        accum_one(tb.z, eb.z, lb.z, repbase, elr);
        accum_one(tb.w, eb.w, lb.w, repbase, elr);
    }
    for (; i < n4; i += stride) {
        int4   tv = t4[i];
        int4   ev = e4[i];
        float4 lv = l4[i];
        accum_one(tv.x, ev.x, lv.x, repbase, elr);
        accum_one(tv.y, ev.y, lv.y, repbase, elr);
        accum_one(tv.z, ev.z, lv.z, repbase, elr);
        accum_one(tv.w, ev.w, lv.w, repbase, elr);
    }
    int base = n4 << 2;
    int rem  = n - base;
    if (tid < rem) accum_one(times[base + tid], events[base + tid], lr[base + tid], repbase, elr);

    float bsum = block_reduce_sum(elr);
    if (threadIdx.x == 0 && bsum != 0.0f) atomicAdd(&g_elr, bsum);
}

// Post-pass: replica reduce (+ re-zero), cross-block suffix scan,
// per-bucket Efron terms (float Stirling), final scalar.
// 64 blocks x 128 threads, one bucket per thread; all blocks resident.
__global__ void __launch_bounds__(POST_THREADS) k_post(float* __restrict__ out, int out_n) {
    int b = blockIdx.x * POST_THREADS + threadIdx.x;   // bucket 0..8191

    // --- phase 1: reduce over replicas + banks, restore zeros ---
    unsigned ne_fix = 0u;       // fix16 non-event risk
    unsigned cnt = 0u;          // event count
    unsigned ers_fix = 0u;      // fix10 event risk
    #pragma unroll
    for (int r = 0; r < NREP; r++) {
        int idx = r * NBINS + b;
        unsigned v0 = g_C[idx];          g_C[idx] = 0u;
        unsigned v1 = g_C[idx + BANK];   g_C[idx + BANK] = 0u;
        ne_fix  += v0;
        cnt     += v1 >> 24;
        ers_fix += v1 & 0x00FFFFFFu;
    }
    int   d    = (int)cnt;
    float ers  = (float)ers_fix * (1.0f / FIX_EV);
    float risk = (float)ne_fix * (1.0f / FIX_NE) + ers;

    // --- phase 2: cross-block suffix scan of risk ---
    float csum = block_reduce_sum(risk);
    if (threadIdx.x == 0) {
        g_chunk[blockIdx.x] = csum;
        __threadfence();
        atomicAdd(&g_done1, 1u);
        while (*((volatile unsigned*)&g_done1) < gridDim.x) { }
    }
    __syncthreads();
    __threadfence();

    float suffix_base = 0.0f;
    for (int j = blockIdx.x + 1; j < POST_BLOCKS; j++) suffix_base += g_chunk[j];

    __shared__ float sv[POST_THREADS];
    sv[threadIdx.x] = risk;
    __syncthreads();
    for (int off = 1; off < POST_THREADS; off <<= 1) {
        float add = (threadIdx.x + off < POST_THREADS) ? sv[threadIdx.x + off] : 0.0f;
        __syncthreads();
        sv[threadIdx.x] += add;
        __syncthreads();
    }
    float rss = suffix_base + sv[threadIdx.x];   // inclusive suffix sum at bucket b

    // --- phase 3: Efron terms (all-float, cancellation-free) ---
    float term = 0.0f;
    if (d == 1) {
        term = logf(rss + 1e-12f);
    } else if (d > 1) {
        float s  = ers / (float)d;
        float x  = rss / s;
        float a  = x + 1.0f;
        float bb = x - (float)d + 1.0f;
        if (bb > 0.5f) {
            // F(z) = (z-1/2)ln z - z + 1/(12z); F(a)-F(b) without cancellation:
            float la = logf(a), lb = logf(bb);
            float L  = 0.5f * (la + lb);
            float m  = 0.5f * (a + bb);
            float dlt = log1pf((float)d / bb);
            term = (float)d * (logf(s) + L - 1.0f)
                 + (m - 0.5f) * dlt
                 + (1.0f / 12.0f) * (1.0f / a - 1.0f / bb);
        } else {   // near-clamp fallback (matches reference per-term max(.,eps))
            float sum = 0.0f;
            for (int l = 0; l < d; l++)
                sum += __logf(fmaxf(rss - (float)l * s, 1e-12f));
            term = sum;
        }
    }
    float tsum = block_reduce_sum(term);
    if (threadIdx.x == 0 && tsum != 0.0f) atomicAdd(&g_terms, tsum);
    float dsum = block_reduce_sum((float)d);
    if (threadIdx.x == 0 && dsum != 0.0f) atomicAdd(&g_nev, dsum);

    // --- phase 4: last block finalizes and resets scalars ---
    __threadfence();
    __shared__ bool s_last;
    __syncthreads();
    if (threadIdx.x == 0) {
        unsigned prev = atomicAdd(&g_done2, 1u);
        s_last = (prev == gridDim.x - 1);
    }
    __syncthreads();
    if (!s_last) return;

    __threadfence();
    float terms = *((volatile float*)&g_terms);
    float elr   = *((volatile float*)&g_elr);
    float nev   = *((volatile float*)&g_nev);
    float val   = (terms - elr) / fmaxf(nev, 1.0f);
    for (int i = threadIdx.x; i < out_n; i += POST_THREADS) out[i] = val;

    if (threadIdx.x == 0) {   // restore all-zero invariant for next replay
        g_elr = 0.0f; g_terms = 0.0f; g_nev = 0.0f;
        g_done1 = 0u; g_done2 = 0u;
    }
}

extern "C" void kernel_launch(void* const* d_in, const int* in_sizes, int n_in,
                              void* d_out, int out_size) {
    const int*   times  = (const int*)d_in[0];
    const int*   events = (const int*)d_in[1];
    const float* lr     = (const float*)d_in[2];
    float*       out    = (float*)d_out;
    int n = in_sizes[0];

    k_accum<<<1184, 256>>>(times, events, lr, n);
    k_post <<<POST_BLOCKS, POST_THREADS>>>(out, out_size);
}